// round 2
// baseline (speedup 1.0000x reference)
#include <cuda_runtime.h>
#include <math_constants.h>

#define N_ROWS  128
#define IN_DIM  1024
#define OUT_DIM 1024

#define TM 32          // n-tile per block
#define TN 32          // o-tile per block
#define KC 64          // k-chunk in smem
#define PAD 4
#define LDSTR (KC + PAD)   // 68 floats: 16B-aligned rows, conflict-benign banks

__global__ __launch_bounds__(256, 1)
void tropical_linear_kernel(const float* __restrict__ x,
                            const float* __restrict__ w,
                            const float* __restrict__ bias,
                            float* __restrict__ out) {
    __shared__ float xs[TM * LDSTR];
    __shared__ float ws[TN * LDSTR];

    const int tx  = threadIdx.x;          // 0..15 -> o direction
    const int ty  = threadIdx.y;          // 0..15 -> n direction
    const int tid = ty * 16 + tx;
    const int n0  = blockIdx.y * TM;
    const int o0  = blockIdx.x * TN;

    float acc[2][2];
    #pragma unroll
    for (int i = 0; i < 2; i++)
        #pragma unroll
        for (int j = 0; j < 2; j++)
            acc[i][j] = -CUDART_INF_F;

    for (int k0 = 0; k0 < IN_DIM; k0 += KC) {
        // Load x tile [TM x KC] and w tile [TN x KC]: 2048 floats each = 512 float4.
        // 256 threads x 2 float4 per array. Coalesced along k.
        #pragma unroll
        for (int i = 0; i < 2; i++) {
            int f   = tid + i * 256;        // 0..511
            int row = f >> 4;               // KC/4 = 16 float4 per row
            int c4  = f & 15;
            float4 vx = *(const float4*)&x[(n0 + row) * IN_DIM + k0 + c4 * 4];
            *(float4*)&xs[row * LDSTR + c4 * 4] = vx;
            float4 vw = *(const float4*)&w[(o0 + row) * IN_DIM + k0 + c4 * 4];
            *(float4*)&ws[row * LDSTR + c4 * 4] = vw;
        }
        __syncthreads();

        #pragma unroll
        for (int kk = 0; kk < KC; kk += 4) {
            float4 xv[2];
            float4 wv[2];
            #pragma unroll
            for (int i = 0; i < 2; i++)
                xv[i] = *(const float4*)&xs[(ty * 2 + i) * LDSTR + kk];
            #pragma unroll
            for (int j = 0; j < 2; j++)
                wv[j] = *(const float4*)&ws[(tx * 2 + j) * LDSTR + kk];

            #pragma unroll
            for (int i = 0; i < 2; i++)
                #pragma unroll
                for (int j = 0; j < 2; j++) {
                    acc[i][j] = fmaxf(acc[i][j], xv[i].x + wv[j].x);
                    acc[i][j] = fmaxf(acc[i][j], xv[i].y + wv[j].y);
                    acc[i][j] = fmaxf(acc[i][j], xv[i].z + wv[j].z);
                    acc[i][j] = fmaxf(acc[i][j], xv[i].w + wv[j].w);
                }
        }
        __syncthreads();
    }

    #pragma unroll
    for (int i = 0; i < 2; i++) {
        int n = n0 + ty * 2 + i;
        #pragma unroll
        for (int j = 0; j < 2; j++) {
            int o = o0 + tx * 2 + j;
            out[n * OUT_DIM + o] = acc[i][j] + bias[o];
        }
    }
}

extern "C" void kernel_launch(void* const* d_in, const int* in_sizes, int n_in,
                              void* d_out, int out_size) {
    const float* x    = (const float*)d_in[0];   // [128, 1024]
    const float* wgt  = (const float*)d_in[1];   // [1024, 1024]
    const float* bias = (const float*)d_in[2];   // [1024]
    float* out        = (float*)d_out;           // [128, 1024]

    dim3 grid(OUT_DIM / TN, N_ROWS / TM);        // (32, 4) = 128 blocks
    dim3 block(16, 16);                          // 256 threads
    tropical_linear_kernel<<<grid, block>>>(x, wgt, bias, out);
}

// round 3
// speedup vs baseline: 1.4908x; 1.4908x over previous
#include <cuda_runtime.h>
#include <math_constants.h>

#define N_ROWS  128
#define IN_DIM  1024
#define OUT_DIM 1024

#define TM 32
#define TN 32
#define KC 64
#define LDSTR 68        // 68 % 32 == 4 -> consecutive rows start 4 banks apart (8 rows cover all 32)

// Packed fp32 pair add (Blackwell sm_103a). ptxas resolves the mov.b64
// pack/unpack into register-pair allocation in the common case.
__device__ __forceinline__ void add2(float a0, float a1, float b0, float b1,
                                     float& s0, float& s1) {
    unsigned long long ra, rb, rc;
    asm("mov.b64 %0, {%1, %2};" : "=l"(ra) : "f"(a0), "f"(a1));
    asm("mov.b64 %0, {%1, %2};" : "=l"(rb) : "f"(b0), "f"(b1));
    asm("add.rn.f32x2 %0, %1, %2;" : "=l"(rc) : "l"(ra), "l"(rb));
    asm("mov.b64 {%0, %1}, %2;" : "=f"(s0), "=f"(s1) : "l"(rc));
}

__device__ __forceinline__ float max4acc(float acc, float s0, float s1, float s2, float s3) {
    return fmaxf(acc, fmaxf(fmaxf(s0, s1), fmaxf(s2, s3)));
}

__global__ __launch_bounds__(256, 1)
void tropical_linear_kernel(const float* __restrict__ x,
                            const float* __restrict__ w,
                            const float* __restrict__ bias,
                            float* __restrict__ out) {
    __shared__ float xs[2][TM * LDSTR];
    __shared__ float ws[2][TN * LDSTR];

    const int tid  = threadIdx.x;
    const int lane = tid & 31;
    const int warp = tid >> 5;            // 0..7
    const int ln   = lane >> 3;           // 0..3  (n direction within warp)
    const int lo   = lane & 7;            // 0..7  (o direction within warp)
    const int wn   = (warp >> 1) * 8;     // warp n-base: 0,8,16,24
    const int wo   = (warp & 1) * 16;     // warp o-base: 0,16

    const int n0 = blockIdx.y * TM;
    const int o0 = blockIdx.x * TN;

    // Global-load assignment: per chunk, each array is 32 rows x 16 float4 = 512 float4.
    // 256 threads x 2 float4 each. Coalesced along k.
    const int f0 = tid,        r0 = f0 >> 4, c0 = f0 & 15;
    const int f1 = tid + 256,  r1 = f1 >> 4, c1 = f1 & 15;

    const float* xg = x + n0 * IN_DIM;
    const float* wg = w + o0 * IN_DIM;

    // Prefetch chunk 0 into registers
    float4 px0 = *(const float4*)&xg[r0 * IN_DIM + c0 * 4];
    float4 px1 = *(const float4*)&xg[r1 * IN_DIM + c1 * 4];
    float4 pw0 = *(const float4*)&wg[r0 * IN_DIM + c0 * 4];
    float4 pw1 = *(const float4*)&wg[r1 * IN_DIM + c1 * 4];

    float acc00 = -CUDART_INF_F, acc01 = -CUDART_INF_F;
    float acc10 = -CUDART_INF_F, acc11 = -CUDART_INF_F;

    // Stage chunk 0
    *(float4*)&xs[0][r0 * LDSTR + c0 * 4] = px0;
    *(float4*)&xs[0][r1 * LDSTR + c1 * 4] = px1;
    *(float4*)&ws[0][r0 * LDSTR + c0 * 4] = pw0;
    *(float4*)&ws[0][r1 * LDSTR + c1 * 4] = pw1;
    __syncthreads();

    const int NCHUNK = IN_DIM / KC;   // 16
    for (int t = 0; t < NCHUNK; ++t) {
        const int buf = t & 1;

        // Prefetch next chunk while computing this one (LDG latency hidden by compute)
        if (t < NCHUNK - 1) {
            const int k0 = (t + 1) * KC;
            px0 = *(const float4*)&xg[r0 * IN_DIM + k0 + c0 * 4];
            px1 = *(const float4*)&xg[r1 * IN_DIM + k0 + c1 * 4];
            pw0 = *(const float4*)&wg[r0 * IN_DIM + k0 + c0 * 4];
            pw1 = *(const float4*)&wg[r1 * IN_DIM + k0 + c1 * 4];
        }

        const float* xb = xs[buf];
        const float* wb = ws[buf];

        #pragma unroll
        for (int kk = 0; kk < KC; kk += 4) {
            // 4 LDS.128, each exactly one conflict-free wavefront:
            //  xv*: 4 distinct consecutive rows (banks 4r..4r+3, r=0..3)  -> 64B
            //  wv*: 8 distinct consecutive rows (banks 4r..4r+3, r=0..7)  -> 128B
            float4 xv0 = *(const float4*)&xb[(wn +      ln) * LDSTR + kk];
            float4 xv1 = *(const float4*)&xb[(wn + 4 +  ln) * LDSTR + kk];
            float4 wv0 = *(const float4*)&wb[(wo +      lo) * LDSTR + kk];
            float4 wv1 = *(const float4*)&wb[(wo + 8 +  lo) * LDSTR + kk];

            float s0, s1, s2, s3;

            add2(xv0.x, xv0.y, wv0.x, wv0.y, s0, s1);
            add2(xv0.z, xv0.w, wv0.z, wv0.w, s2, s3);
            acc00 = max4acc(acc00, s0, s1, s2, s3);

            add2(xv0.x, xv0.y, wv1.x, wv1.y, s0, s1);
            add2(xv0.z, xv0.w, wv1.z, wv1.w, s2, s3);
            acc01 = max4acc(acc01, s0, s1, s2, s3);

            add2(xv1.x, xv1.y, wv0.x, wv0.y, s0, s1);
            add2(xv1.z, xv1.w, wv0.z, wv0.w, s2, s3);
            acc10 = max4acc(acc10, s0, s1, s2, s3);

            add2(xv1.x, xv1.y, wv1.x, wv1.y, s0, s1);
            add2(xv1.z, xv1.w, wv1.z, wv1.w, s2, s3);
            acc11 = max4acc(acc11, s0, s1, s2, s3);
        }

        // Stage next chunk into the other buffer. Its last readers finished
        // before the barrier that ended iteration t-1, so this is safe; the
        // barrier below publishes it for iteration t+1.
        if (t < NCHUNK - 1) {
            const int nb = buf ^ 1;
            *(float4*)&xs[nb][r0 * LDSTR + c0 * 4] = px0;
            *(float4*)&xs[nb][r1 * LDSTR + c1 * 4] = px1;
            *(float4*)&ws[nb][r0 * LDSTR + c0 * 4] = pw0;
            *(float4*)&ws[nb][r1 * LDSTR + c1 * 4] = pw1;
        }
        __syncthreads();
    }

    const int n_a = n0 + wn + ln;
    const int n_b = n_a + 4;
    const int o_a = o0 + wo + lo;
    const int o_b = o_a + 8;
    const float ba = bias[o_a];
    const float bb = bias[o_b];

    out[n_a * OUT_DIM + o_a] = acc00 + ba;
    out[n_a * OUT_DIM + o_b] = acc01 + bb;
    out[n_b * OUT_DIM + o_a] = acc10 + ba;
    out[n_b * OUT_DIM + o_b] = acc11 + bb;
}

extern "C" void kernel_launch(void* const* d_in, const int* in_sizes, int n_in,
                              void* d_out, int out_size) {
    const float* x    = (const float*)d_in[0];   // [128, 1024]
    const float* wgt  = (const float*)d_in[1];   // [1024, 1024]
    const float* bias = (const float*)d_in[2];   // [1024]
    float* out        = (float*)d_out;           // [128, 1024]

    dim3 grid(OUT_DIM / TN, N_ROWS / TM);        // (32, 4) = 128 blocks, one wave
    dim3 block(256);
    tropical_linear_kernel<<<grid, block>>>(x, wgt, bias, out);
}